// round 15
// baseline (speedup 1.0000x reference)
#include <cuda_runtime.h>
#include <math.h>
#include <stdint.h>

#define PB   8
#define PT   128
#define PC   1024
#define PH   16
#define PD   64
#define PCAP 2048
#define PHALF 32
#define M1 (PB*PT)   // 1024
#define N1 (3*PC)    // 3072
#define NCHUNK 4
#define CHUNK (PCAP/NCHUNK)   // 512
#define TS   64               // KV tile (slots)
#define NT   (CHUNK/TS)       // 8

// ---------------- scratch ----------------
__device__ float g_q [PB*PH*PT*PD];
__device__ float g_kn[PB*PH*PT*PD];
__device__ float g_vn[PB*PH*PT*PD];
__device__ float g_att[PB*PT*PC];
__device__ float g_po[NCHUNK * PB*PH * PT * PD];
__device__ float g_pm[NCHUNK * PB*PH * PT];
__device__ float g_pl[NCHUNK * PB*PH * PT];
__device__ float g_cs[M1 * PHALF];
__device__ float g_sn[M1 * PHALF];

// ---------------- TF32 helpers ---------------------------------------------
__device__ __forceinline__ uint32_t f2tf32(float x) {
    uint32_t r;
    asm("cvt.rna.tf32.f32 %0, %1;" : "=r"(r) : "f"(x));
    return r;
}

__device__ __forceinline__ void mma_tf32(float c[4], const uint32_t a[4], const uint32_t b[2]) {
    asm volatile(
        "mma.sync.aligned.m16n8k8.row.col.f32.tf32.tf32.f32 "
        "{%0,%1,%2,%3}, {%4,%5,%6,%7}, {%8,%9}, {%0,%1,%2,%3};"
        : "+f"(c[0]), "+f"(c[1]), "+f"(c[2]), "+f"(c[3])
        : "r"(a[0]), "r"(a[1]), "r"(a[2]), "r"(a[3]), "r"(b[0]), "r"(b[1]));
}

__device__ __forceinline__ void cp_async16(uint32_t saddr, const void* g) {
    asm volatile("cp.async.cg.shared.global [%0], [%1], 16;" :: "r"(saddr), "l"(g));
}
__device__ __forceinline__ void cp_commit() {
    asm volatile("cp.async.commit_group;");
}
__device__ __forceinline__ void cp_wait0() {
    asm volatile("cp.async.wait_group 0;");
}

// ---------------- rope trig table ------------------------------------------
__global__ __launch_bounds__(256)
void rope_trig_kernel(const int* __restrict__ end_offset)
{
    int idx = blockIdx.x * 256 + threadIdx.x;
    int j = idx & (PHALF - 1);
    int row = idx >> 5;
    int b = row >> 7;
    int t = row & (PT - 1);
    int ts = end_offset[b] + t;
    float freq = expf((float)j * (-logf(10000.0f) * 2.0f / (float)PD));
    float ang = (float)ts * freq;
    g_cs[idx] = cosf(ang);
    g_sn[idx] = sinf(ang);
}

// ---------------- GEMM1: x @ w_in^T with fused rope + scatter ---------------
#define GBK 32
#define GPW 36
__global__ __launch_bounds__(256)
void gemm_qkv_tf32_kernel(const float* __restrict__ A, const float* __restrict__ Bm)
{
    __shared__ float As[2][64][GPW];
    __shared__ float Bs[2][128][GPW];

    const int K = PC;
    const int bm = blockIdx.y * 64;
    const int bn = blockIdx.x * 128;
    const int tid = threadIdx.x;
    const int warp = tid >> 5;
    const int lane = tid & 31;
    const int wm = (warp >> 2) * 32;
    const int wn = (warp & 3) * 32;
    const int gid = lane >> 2;
    const int tig = lane & 3;

    const uint32_t as_base = (uint32_t)__cvta_generic_to_shared(&As[0][0][0]);
    const uint32_t bs_base = (uint32_t)__cvta_generic_to_shared(&Bs[0][0][0]);

    float acc[2][4][4];
#pragma unroll
    for (int i = 0; i < 2; i++)
#pragma unroll
        for (int j = 0; j < 4; j++)
#pragma unroll
            for (int c = 0; c < 4; c++) acc[i][j][c] = 0.f;

    auto prefetch = [&](int k0, int buf) {
#pragma unroll
        for (int p = 0; p < 2; p++) {
            int idx = tid + p * 256;
            int row = idx >> 3;
            int c4 = (idx & 7) << 2;
            cp_async16(as_base + ((buf * 64 + row) * GPW + c4) * 4u,
                       &A[(size_t)(bm + row) * K + k0 + c4]);
        }
#pragma unroll
        for (int p = 0; p < 4; p++) {
            int idx = tid + p * 256;
            int row = idx >> 3;
            int c4 = (idx & 7) << 2;
            cp_async16(bs_base + ((buf * 128 + row) * GPW + c4) * 4u,
                       &Bm[(size_t)(bn + row) * K + k0 + c4]);
        }
        cp_commit();
    };

    prefetch(0, 0);
    int buf = 0;
    const int niter = K / GBK;

    for (int it = 0; it < niter; it++) {
        cp_wait0();
        __syncthreads();
        if (it + 1 < niter) prefetch((it + 1) * GBK, buf ^ 1);

#pragma unroll
        for (int ks = 0; ks < 4; ks++) {
            int kk = ks * 8;
            uint32_t af[2][4], bf[4][2];
#pragma unroll
            for (int mi = 0; mi < 2; mi++) {
                int r = wm + mi * 16 + gid;
                af[mi][0] = f2tf32(As[buf][r    ][kk + tig]);
                af[mi][1] = f2tf32(As[buf][r + 8][kk + tig]);
                af[mi][2] = f2tf32(As[buf][r    ][kk + tig + 4]);
                af[mi][3] = f2tf32(As[buf][r + 8][kk + tig + 4]);
            }
#pragma unroll
            for (int ni = 0; ni < 4; ni++) {
                int r = wn + ni * 8 + gid;
                bf[ni][0] = f2tf32(Bs[buf][r][kk + tig]);
                bf[ni][1] = f2tf32(Bs[buf][r][kk + tig + 4]);
            }
#pragma unroll
            for (int mi = 0; mi < 2; mi++)
#pragma unroll
                for (int ni = 0; ni < 4; ni++)
                    mma_tf32(acc[mi][ni], af[mi], bf[ni]);
        }
        __syncthreads();
        buf ^= 1;
    }

    // ---- fused rope epilogue ----
#pragma unroll
    for (int mi = 0; mi < 2; mi++) {
        int row0 = bm + wm + mi * 16 + gid;
#pragma unroll
        for (int ni = 0; ni < 4; ni++) {
            int col = bn + wn + ni * 8 + tig * 2;
            int p = col >> 10;
            int h = (col >> 6) & (PH - 1);
            int d = col & (PD - 1);
            int j = d >> 1;
#pragma unroll
            for (int rr = 0; rr < 2; rr++) {
                int row = row0 + rr * 8;
                float c0 = acc[mi][ni][rr * 2];
                float c1 = acc[mi][ni][rr * 2 + 1];
                int b = row >> 7;
                int t = row & (PT - 1);
                size_t dst = ((size_t)((b * PH + h) * PT + t)) * PD + d;
                if (p == 2) {
                    *(float2*)&g_vn[dst] = make_float2(c0, c1);
                } else {
                    float cs = g_cs[row * PHALF + j];
                    float sn = g_sn[row * PHALF + j];
                    float o0 = c0 * cs - c1 * sn;
                    float o1 = c0 * sn + c1 * cs;
                    float* out = (p == 0) ? g_q : g_kn;
                    *(float2*)&out[dst] = make_float2(o0, o1);
                }
            }
        }
    }
}

// ---------------- GEMM2: generic NT (double-buffered) -----------------------
__global__ __launch_bounds__(256)
void gemm_nt_tf32_kernel(const float* __restrict__ A, const float* __restrict__ Bm,
                         float* __restrict__ Cout, int M, int N, int K)
{
    __shared__ float As[2][64][GPW];
    __shared__ float Bs[2][128][GPW];

    const int bm = blockIdx.y * 64;
    const int bn = blockIdx.x * 128;
    const int tid = threadIdx.x;
    const int warp = tid >> 5;
    const int lane = tid & 31;
    const int wm = (warp >> 2) * 32;
    const int wn = (warp & 3) * 32;
    const int gid = lane >> 2;
    const int tig = lane & 3;

    const uint32_t as_base = (uint32_t)__cvta_generic_to_shared(&As[0][0][0]);
    const uint32_t bs_base = (uint32_t)__cvta_generic_to_shared(&Bs[0][0][0]);

    float acc[2][4][4];
#pragma unroll
    for (int i = 0; i < 2; i++)
#pragma unroll
        for (int j = 0; j < 4; j++)
#pragma unroll
            for (int c = 0; c < 4; c++) acc[i][j][c] = 0.f;

    auto prefetch = [&](int k0, int buf) {
#pragma unroll
        for (int p = 0; p < 2; p++) {
            int idx = tid + p * 256;
            int row = idx >> 3;
            int c4 = (idx & 7) << 2;
            cp_async16(as_base + ((buf * 64 + row) * GPW + c4) * 4u,
                       &A[(size_t)(bm + row) * K + k0 + c4]);
        }
#pragma unroll
        for (int p = 0; p < 4; p++) {
            int idx = tid + p * 256;
            int row = idx >> 3;
            int c4 = (idx & 7) << 2;
            cp_async16(bs_base + ((buf * 128 + row) * GPW + c4) * 4u,
                       &Bm[(size_t)(bn + row) * K + k0 + c4]);
        }
        cp_commit();
    };

    prefetch(0, 0);
    int buf = 0;
    const int niter = K / GBK;

    for (int it = 0; it < niter; it++) {
        cp_wait0();
        __syncthreads();
        if (it + 1 < niter) prefetch((it + 1) * GBK, buf ^ 1);

#pragma unroll
        for (int ks = 0; ks < 4; ks++) {
            int kk = ks * 8;
            uint32_t af[2][4], bf[4][2];
#pragma unroll
            for (int mi = 0; mi < 2; mi++) {
                int r = wm + mi * 16 + gid;
                af[mi][0] = f2tf32(As[buf][r    ][kk + tig]);
                af[mi][1] = f2tf32(As[buf][r + 8][kk + tig]);
                af[mi][2] = f2tf32(As[buf][r    ][kk + tig + 4]);
                af[mi][3] = f2tf32(As[buf][r + 8][kk + tig + 4]);
            }
#pragma unroll
            for (int ni = 0; ni < 4; ni++) {
                int r = wn + ni * 8 + gid;
                bf[ni][0] = f2tf32(Bs[buf][r][kk + tig]);
                bf[ni][1] = f2tf32(Bs[buf][r][kk + tig + 4]);
            }
#pragma unroll
            for (int mi = 0; mi < 2; mi++)
#pragma unroll
                for (int ni = 0; ni < 4; ni++)
                    mma_tf32(acc[mi][ni], af[mi], bf[ni]);
        }
        __syncthreads();
        buf ^= 1;
    }

#pragma unroll
    for (int mi = 0; mi < 2; mi++) {
#pragma unroll
        for (int ni = 0; ni < 4; ni++) {
            int row = bm + wm + mi * 16 + gid;
            int col = bn + wn + ni * 8 + tig * 2;
            *(float2*)&Cout[(size_t)row * N + col] =
                make_float2(acc[mi][ni][0], acc[mi][ni][1]);
            *(float2*)&Cout[(size_t)(row + 8) * N + col] =
                make_float2(acc[mi][ni][2], acc[mi][ni][3]);
        }
    }
}

// ---------------- tensor-core split-KV flash attention (TS=64) --------------
// Q fragments reloaded from L1 each tile (frees 32 regs); 2 blocks/SM forced.
#define KSP 68
#define VSP 72
__global__ __launch_bounds__(256, 2)
void attn_mma_kernel(const float* __restrict__ cache_k,
                     const float* __restrict__ cache_v,
                     const int* __restrict__ end_offset)
{
    __shared__ __align__(16) float Ks[2][TS][KSP];
    __shared__ __align__(16) float Vs[2][TS][VSP];

    const int bh = blockIdx.x;
    const int chunk = blockIdx.y;
    const int b = bh / PH;
    const int tid = threadIdx.x;
    const int warp = tid >> 5;
    const int lane = tid & 31;
    const int gid = lane >> 2;
    const int tig = lane & 3;
    const int stripe = warp * 16;

    const int end = end_offset[b];
    const int last = end + PT - 1;
    const int end_index = last % PCAP;
    const int new_end = end + PT;    // exec_mask all-true by construction

    const uint32_t ks_base = (uint32_t)__cvta_generic_to_shared(&Ks[0][0][0]);
    const uint32_t vs_base = (uint32_t)__cvta_generic_to_shared(&Vs[0][0][0]);

    float m0 = -1e30f, m1 = -1e30f, l0 = 0.f, l1 = 0.f;
    const int tsq0 = end + stripe + gid;
    const int tsq1 = tsq0 + 8;

    float o[8][4];
#pragma unroll
    for (int ni = 0; ni < 8; ni++)
#pragma unroll
        for (int c = 0; c < 4; c++) o[ni][c] = 0.f;

    const size_t kv_base_new   = (size_t)bh * PT * PD;
    const size_t kv_base_cache = (size_t)bh * PCAP * PD;
    const int s_begin = chunk * CHUNK;

    int n_active = (new_end - s_begin + TS - 1) >> 6;
    if (n_active < 0) n_active = 0;
    if (n_active > NT) n_active = NT;

    const int w0 = end & (PCAP - 1);
    const int w1 = last & (PCAP - 1);
    const bool wrapped = w1 < w0;

    // Q row pointers (L1-resident after first tile)
    const float* qr0 = &g_q[(size_t)bh * PT * PD + (size_t)(stripe + gid) * PD];
    const float* qr1 = qr0 + 8 * PD;

    auto prefetch = [&](int tile, int buf) {
        const int s0 = s_begin + tile * TS;
#pragma unroll
        for (int p = 0; p < 4; p++) {
            int idx = tid + p * 256;     // 0..1023: 64 slots x 16 float4
            int slot = idx >> 4;
            int c4 = (idx & 15) * 4;
            int s = s0 + slot;
            int trel = s - end; if (trel < 0) trel += PCAP;
            const float *srcK, *srcV;
            if (trel < PT) {
                srcK = &g_kn[kv_base_new + (size_t)trel * PD];
                srcV = &g_vn[kv_base_new + (size_t)trel * PD];
            } else {
                srcK = &cache_k[kv_base_cache + (size_t)s * PD];
                srcV = &cache_v[kv_base_cache + (size_t)s * PD];
            }
            cp_async16(ks_base + ((buf * TS + slot) * KSP + c4) * 4u, srcK + c4);
            cp_async16(vs_base + ((buf * TS + slot) * VSP + c4) * 4u, srcV + c4);
        }
        cp_commit();
    };

    if (n_active > 0) prefetch(0, 0);
    int buf = 0;

    for (int tile = 0; tile < n_active; tile++) {
        const int s0 = s_begin + tile * TS;
        const int s_last = s0 + TS - 1;
        const bool has_new = wrapped ? ((s_last >= w0) | (s0 <= w1))
                                     : ((s_last >= w0) & (s0 <= w1));
        const bool has_inv = (s_last >= new_end);
        const bool needs_mask = has_new | has_inv;

        cp_wait0();
        __syncthreads();

        if (tile + 1 < n_active) prefetch(tile + 1, buf ^ 1);

        // ---- S = Q K^T : per warp 16x64; Q frags reloaded (L1 hits) ----
        float sacc[8][4];
        uint32_t* sbits = reinterpret_cast<uint32_t*>(&sacc[0][0]);
#pragma unroll
        for (int ni = 0; ni < 8; ni++)
#pragma unroll
            for (int c = 0; c < 4; c++) sacc[ni][c] = 0.f;
#pragma unroll
        for (int kt = 0; kt < 8; kt++) {
            uint32_t qa[4];
            qa[0] = f2tf32(__ldg(&qr0[kt * 8 + tig]));
            qa[1] = f2tf32(__ldg(&qr1[kt * 8 + tig]));
            qa[2] = f2tf32(__ldg(&qr0[kt * 8 + tig + 4]));
            qa[3] = f2tf32(__ldg(&qr1[kt * 8 + tig + 4]));
            uint32_t bf[8][2];
#pragma unroll
            for (int ni = 0; ni < 8; ni++) {
                bf[ni][0] = f2tf32(Ks[buf][ni * 8 + gid][kt * 8 + tig]);
                bf[ni][1] = f2tf32(Ks[buf][ni * 8 + gid][kt * 8 + tig + 4]);
            }
#pragma unroll
            for (int ni = 0; ni < 8; ni++)
                mma_tf32(sacc[ni], qa, bf[ni]);
        }

        // ---- mask + scale ----
        if (needs_mask) {
#pragma unroll
            for (int ni = 0; ni < 8; ni++) {
#pragma unroll
                for (int half = 0; half < 2; half++) {
                    int col = ni * 8 + 2 * tig + half;
                    int s = s0 + col;
                    int delta = s - end_index;
                    int p = (delta <= 0) ? (last + delta) : (last + delta - PCAP);
                    if (s >= new_end) p = -1;
                    int d0 = tsq0 - p, d1 = tsq1 - p;
                    bool v0 = (p >= 0) & (d0 >= 0) & (d0 < PCAP);
                    bool v1 = (p >= 0) & (d1 >= 0) & (d1 < PCAP);
                    sacc[ni][half]     = v0 ? sacc[ni][half] * 0.125f     : -1e9f;
                    sacc[ni][half + 2] = v1 ? sacc[ni][half + 2] * 0.125f : -1e9f;
                }
            }
        } else {
#pragma unroll
            for (int ni = 0; ni < 8; ni++)
#pragma unroll
                for (int c = 0; c < 4; c++) sacc[ni][c] *= 0.125f;
        }

        // ---- register softmax ----
        float mx0 = -1e30f, mx1 = -1e30f;
#pragma unroll
        for (int ni = 0; ni < 8; ni++) {
            mx0 = fmaxf(mx0, fmaxf(sacc[ni][0], sacc[ni][1]));
            mx1 = fmaxf(mx1, fmaxf(sacc[ni][2], sacc[ni][3]));
        }
        mx0 = fmaxf(mx0, __shfl_xor_sync(0xFFFFFFFFu, mx0, 1));
        mx0 = fmaxf(mx0, __shfl_xor_sync(0xFFFFFFFFu, mx0, 2));
        mx1 = fmaxf(mx1, __shfl_xor_sync(0xFFFFFFFFu, mx1, 1));
        mx1 = fmaxf(mx1, __shfl_xor_sync(0xFFFFFFFFu, mx1, 2));
        float mn0 = fmaxf(m0, mx0), mn1 = fmaxf(m1, mx1);
        float a0 = __expf(m0 - mn0), a1 = __expf(m1 - mn1);
        m0 = mn0; m1 = mn1;

        float ls0 = 0.f, ls1 = 0.f;
#pragma unroll
        for (int ni = 0; ni < 8; ni++) {
            float p0 = __expf(sacc[ni][0] - mn0);
            float p1 = __expf(sacc[ni][1] - mn0);
            float p2 = __expf(sacc[ni][2] - mn1);
            float p3 = __expf(sacc[ni][3] - mn1);
            ls0 += p0 + p1;  ls1 += p2 + p3;
            sbits[ni * 4 + 0] = f2tf32(p0); sbits[ni * 4 + 1] = f2tf32(p1);
            sbits[ni * 4 + 2] = f2tf32(p2); sbits[ni * 4 + 3] = f2tf32(p3);
        }
        ls0 += __shfl_xor_sync(0xFFFFFFFFu, ls0, 1);
        ls0 += __shfl_xor_sync(0xFFFFFFFFu, ls0, 2);
        ls1 += __shfl_xor_sync(0xFFFFFFFFu, ls1, 1);
        ls1 += __shfl_xor_sync(0xFFFFFFFFu, ls1, 2);
        l0 = l0 * a0 + ls0;
        l1 = l1 * a1 + ls1;

        // ---- rescale O ----
#pragma unroll
        for (int ni = 0; ni < 8; ni++) {
            o[ni][0] *= a0; o[ni][1] *= a0;
            o[ni][2] *= a1; o[ni][3] *= a1;
        }

        // ---- O += P V : shfl permute C-frag -> A-frag (8 k-chunks) ----
        const int lbase = lane & ~3;
        const int lsrc0 = lbase + (tig >> 1);
        const int lsrc2 = lsrc0 + 2;
        const bool odd = tig & 1;
#pragma unroll
        for (int kt = 0; kt < 8; kt++) {
            uint32_t x0 = __shfl_sync(0xFFFFFFFFu, sbits[kt * 4 + 0], lsrc0);
            uint32_t x1 = __shfl_sync(0xFFFFFFFFu, sbits[kt * 4 + 1], lsrc0);
            uint32_t y0 = __shfl_sync(0xFFFFFFFFu, sbits[kt * 4 + 2], lsrc0);
            uint32_t y1 = __shfl_sync(0xFFFFFFFFu, sbits[kt * 4 + 3], lsrc0);
            uint32_t x2 = __shfl_sync(0xFFFFFFFFu, sbits[kt * 4 + 0], lsrc2);
            uint32_t x3 = __shfl_sync(0xFFFFFFFFu, sbits[kt * 4 + 1], lsrc2);
            uint32_t y2 = __shfl_sync(0xFFFFFFFFu, sbits[kt * 4 + 2], lsrc2);
            uint32_t y3 = __shfl_sync(0xFFFFFFFFu, sbits[kt * 4 + 3], lsrc2);
            uint32_t pa[4];
            pa[0] = odd ? x1 : x0;
            pa[1] = odd ? y1 : y0;
            pa[2] = odd ? x3 : x2;
            pa[3] = odd ? y3 : y2;
#pragma unroll
            for (int ni = 0; ni < 8; ni++) {
                uint32_t bf[2];
                bf[0] = f2tf32(Vs[buf][kt * 8 + tig    ][ni * 8 + gid]);
                bf[1] = f2tf32(Vs[buf][kt * 8 + tig + 4][ni * 8 + gid]);
                mma_tf32(o[ni], pa, bf);
            }
        }
        __syncthreads();
        buf ^= 1;
    }

    const size_t prowbase = (size_t)(chunk * PB * PH + bh) * PT;
    {
        int r0 = stripe + gid, r1 = stripe + gid + 8;
#pragma unroll
        for (int ni = 0; ni < 8; ni++) {
            int col = ni * 8 + tig * 2;
            *(float2*)&g_po[(prowbase + r0) * PD + col] = make_float2(o[ni][0], o[ni][1]);
            *(float2*)&g_po[(prowbase + r1) * PD + col] = make_float2(o[ni][2], o[ni][3]);
        }
        if (tig == 0) {
            g_pm[prowbase + r0] = m0;  g_pl[prowbase + r0] = l0;
            g_pm[prowbase + r1] = m1;  g_pl[prowbase + r1] = l1;
        }
    }
}

// ---------------- combine partials -----------------------------------------
__global__ __launch_bounds__(256)
void attn_combine_kernel()
{
    int gid = blockIdx.x * 256 + threadIdx.x;
    int row = gid >> 4;
    int q4 = (gid & 15) << 2;

    const int RSTRIDE = PB * PH * PT;
    float mv[NCHUNK];
    float mx = -1e30f;
#pragma unroll
    for (int c = 0; c < NCHUNK; c++) {
        mv[c] = g_pm[c * RSTRIDE + row];
        mx = fmaxf(mx, mv[c]);
    }
    float l = 0.f;
    float4 acc = make_float4(0.f, 0.f, 0.f, 0.f);
#pragma unroll
    for (int c = 0; c < NCHUNK; c++) {
        float w = __expf(mv[c] - mx);
        l = fmaf(g_pl[c * RSTRIDE + row], w, l);
        float4 v = *(const float4*)&g_po[((size_t)(c * RSTRIDE) + row) * PD + q4];
        acc.x = fmaf(w, v.x, acc.x); acc.y = fmaf(w, v.y, acc.y);
        acc.z = fmaf(w, v.z, acc.z); acc.w = fmaf(w, v.w, acc.w);
    }
    float inv = 1.0f / l;

    int b = row >> 11;
    int h = (row >> 7) & (PH - 1);
    int t = row & (PT - 1);
    float* op = &g_att[(size_t)(b * PT + t) * PC + h * PD + q4];
    *(float4*)op = make_float4(acc.x * inv, acc.y * inv, acc.z * inv, acc.w * inv);
}

// ---------------- launch ---------------------------------------------------
extern "C" void kernel_launch(void* const* d_in, const int* in_sizes, int n_in,
                              void* d_out, int out_size)
{
    const float* x       = (const float*)d_in[0];
    const float* w_in    = (const float*)d_in[1];
    const float* w_out   = (const float*)d_in[2];
    const float* cache_k = (const float*)d_in[3];
    const float* cache_v = (const float*)d_in[4];
    const int*   end_off = (const int*)d_in[5];
    float* out = (float*)d_out;

    float* att;  cudaGetSymbolAddress((void**)&att,  g_att);

    rope_trig_kernel<<<(M1 * PHALF) / 256, 256>>>(end_off);
    gemm_qkv_tf32_kernel<<<dim3(N1 / 128, M1 / 64), 256>>>(x, w_in);
    attn_mma_kernel<<<dim3(PB * PH, NCHUNK), 256>>>(cache_k, cache_v, end_off);
    attn_combine_kernel<<<(PB * PH * PT * PD / 4) / 256, 256>>>();
    gemm_nt_tf32_kernel<<<dim3(PC / 128, M1 / 64), 256>>>(att, w_out, out, M1, PC, PC);
}

// round 16
// speedup vs baseline: 1.0966x; 1.0966x over previous
#include <cuda_runtime.h>
#include <math.h>
#include <stdint.h>

#define PB   8
#define PT   128
#define PC   1024
#define PH   16
#define PD   64
#define PCAP 2048
#define PHALF 32
#define M1 (PB*PT)   // 1024
#define N1 (3*PC)    // 3072
#define NCHUNK 4
#define CHUNK (PCAP/NCHUNK)   // 512
#define TS   64               // KV tile (slots)
#define NT   (CHUNK/TS)       // 8

// ---------------- scratch ----------------
__device__ float g_q [PB*PH*PT*PD];
__device__ float g_kn[PB*PH*PT*PD];
__device__ float g_vn[PB*PH*PT*PD];
__device__ float g_att[PB*PT*PC];
__device__ float g_po[NCHUNK * PB*PH * PT * PD];
__device__ float g_pm[NCHUNK * PB*PH * PT];
__device__ float g_pl[NCHUNK * PB*PH * PT];
__device__ float g_cs[M1 * PHALF];
__device__ float g_sn[M1 * PHALF];

// ---------------- TF32 helpers ---------------------------------------------
__device__ __forceinline__ uint32_t f2tf32(float x) {
    uint32_t r;
    asm("cvt.rna.tf32.f32 %0, %1;" : "=r"(r) : "f"(x));
    return r;
}

__device__ __forceinline__ void mma_tf32(float c[4], const uint32_t a[4], const uint32_t b[2]) {
    asm volatile(
        "mma.sync.aligned.m16n8k8.row.col.f32.tf32.tf32.f32 "
        "{%0,%1,%2,%3}, {%4,%5,%6,%7}, {%8,%9}, {%0,%1,%2,%3};"
        : "+f"(c[0]), "+f"(c[1]), "+f"(c[2]), "+f"(c[3])
        : "r"(a[0]), "r"(a[1]), "r"(a[2]), "r"(a[3]), "r"(b[0]), "r"(b[1]));
}

__device__ __forceinline__ void cp_async16(uint32_t saddr, const void* g) {
    asm volatile("cp.async.cg.shared.global [%0], [%1], 16;" :: "r"(saddr), "l"(g));
}
__device__ __forceinline__ void cp_commit() {
    asm volatile("cp.async.commit_group;");
}
__device__ __forceinline__ void cp_wait0() {
    asm volatile("cp.async.wait_group 0;");
}

// ---------------- rope trig table ------------------------------------------
__global__ __launch_bounds__(256)
void rope_trig_kernel(const int* __restrict__ end_offset)
{
    int idx = blockIdx.x * 256 + threadIdx.x;
    int j = idx & (PHALF - 1);
    int row = idx >> 5;
    int b = row >> 7;
    int t = row & (PT - 1);
    int ts = end_offset[b] + t;
    float freq = expf((float)j * (-logf(10000.0f) * 2.0f / (float)PD));
    float ang = (float)ts * freq;
    g_cs[idx] = cosf(ang);
    g_sn[idx] = sinf(ang);
}

// ---------------- GEMM1: x @ w_in^T with fused rope + scatter ---------------
#define GBK 32
#define GPW 36
__global__ __launch_bounds__(256)
void gemm_qkv_tf32_kernel(const float* __restrict__ A, const float* __restrict__ Bm)
{
    __shared__ float As[2][64][GPW];
    __shared__ float Bs[2][128][GPW];

    const int K = PC;
    const int bm = blockIdx.y * 64;
    const int bn = blockIdx.x * 128;
    const int tid = threadIdx.x;
    const int warp = tid >> 5;
    const int lane = tid & 31;
    const int wm = (warp >> 2) * 32;
    const int wn = (warp & 3) * 32;
    const int gid = lane >> 2;
    const int tig = lane & 3;

    const uint32_t as_base = (uint32_t)__cvta_generic_to_shared(&As[0][0][0]);
    const uint32_t bs_base = (uint32_t)__cvta_generic_to_shared(&Bs[0][0][0]);

    float acc[2][4][4];
#pragma unroll
    for (int i = 0; i < 2; i++)
#pragma unroll
        for (int j = 0; j < 4; j++)
#pragma unroll
            for (int c = 0; c < 4; c++) acc[i][j][c] = 0.f;

    auto prefetch = [&](int k0, int buf) {
#pragma unroll
        for (int p = 0; p < 2; p++) {
            int idx = tid + p * 256;
            int row = idx >> 3;
            int c4 = (idx & 7) << 2;
            cp_async16(as_base + ((buf * 64 + row) * GPW + c4) * 4u,
                       &A[(size_t)(bm + row) * K + k0 + c4]);
        }
#pragma unroll
        for (int p = 0; p < 4; p++) {
            int idx = tid + p * 256;
            int row = idx >> 3;
            int c4 = (idx & 7) << 2;
            cp_async16(bs_base + ((buf * 128 + row) * GPW + c4) * 4u,
                       &Bm[(size_t)(bn + row) * K + k0 + c4]);
        }
        cp_commit();
    };

    prefetch(0, 0);
    int buf = 0;
    const int niter = K / GBK;

    for (int it = 0; it < niter; it++) {
        cp_wait0();
        __syncthreads();
        if (it + 1 < niter) prefetch((it + 1) * GBK, buf ^ 1);

#pragma unroll
        for (int ks = 0; ks < 4; ks++) {
            int kk = ks * 8;
            uint32_t af[2][4], bf[4][2];
#pragma unroll
            for (int mi = 0; mi < 2; mi++) {
                int r = wm + mi * 16 + gid;
                af[mi][0] = f2tf32(As[buf][r    ][kk + tig]);
                af[mi][1] = f2tf32(As[buf][r + 8][kk + tig]);
                af[mi][2] = f2tf32(As[buf][r    ][kk + tig + 4]);
                af[mi][3] = f2tf32(As[buf][r + 8][kk + tig + 4]);
            }
#pragma unroll
            for (int ni = 0; ni < 4; ni++) {
                int r = wn + ni * 8 + gid;
                bf[ni][0] = f2tf32(Bs[buf][r][kk + tig]);
                bf[ni][1] = f2tf32(Bs[buf][r][kk + tig + 4]);
            }
#pragma unroll
            for (int mi = 0; mi < 2; mi++)
#pragma unroll
                for (int ni = 0; ni < 4; ni++)
                    mma_tf32(acc[mi][ni], af[mi], bf[ni]);
        }
        __syncthreads();
        buf ^= 1;
    }

    // ---- fused rope epilogue ----
#pragma unroll
    for (int mi = 0; mi < 2; mi++) {
        int row0 = bm + wm + mi * 16 + gid;
#pragma unroll
        for (int ni = 0; ni < 4; ni++) {
            int col = bn + wn + ni * 8 + tig * 2;
            int p = col >> 10;
            int h = (col >> 6) & (PH - 1);
            int d = col & (PD - 1);
            int j = d >> 1;
#pragma unroll
            for (int rr = 0; rr < 2; rr++) {
                int row = row0 + rr * 8;
                float c0 = acc[mi][ni][rr * 2];
                float c1 = acc[mi][ni][rr * 2 + 1];
                int b = row >> 7;
                int t = row & (PT - 1);
                size_t dst = ((size_t)((b * PH + h) * PT + t)) * PD + d;
                if (p == 2) {
                    *(float2*)&g_vn[dst] = make_float2(c0, c1);
                } else {
                    float cs = g_cs[row * PHALF + j];
                    float sn = g_sn[row * PHALF + j];
                    float o0 = c0 * cs - c1 * sn;
                    float o1 = c0 * sn + c1 * cs;
                    float* out = (p == 0) ? g_q : g_kn;
                    *(float2*)&out[dst] = make_float2(o0, o1);
                }
            }
        }
    }
}

// ---------------- GEMM2: generic NT (double-buffered) -----------------------
__global__ __launch_bounds__(256)
void gemm_nt_tf32_kernel(const float* __restrict__ A, const float* __restrict__ Bm,
                         float* __restrict__ Cout, int M, int N, int K)
{
    __shared__ float As[2][64][GPW];
    __shared__ float Bs[2][128][GPW];

    const int bm = blockIdx.y * 64;
    const int bn = blockIdx.x * 128;
    const int tid = threadIdx.x;
    const int warp = tid >> 5;
    const int lane = tid & 31;
    const int wm = (warp >> 2) * 32;
    const int wn = (warp & 3) * 32;
    const int gid = lane >> 2;
    const int tig = lane & 3;

    const uint32_t as_base = (uint32_t)__cvta_generic_to_shared(&As[0][0][0]);
    const uint32_t bs_base = (uint32_t)__cvta_generic_to_shared(&Bs[0][0][0]);

    float acc[2][4][4];
#pragma unroll
    for (int i = 0; i < 2; i++)
#pragma unroll
        for (int j = 0; j < 4; j++)
#pragma unroll
            for (int c = 0; c < 4; c++) acc[i][j][c] = 0.f;

    auto prefetch = [&](int k0, int buf) {
#pragma unroll
        for (int p = 0; p < 2; p++) {
            int idx = tid + p * 256;
            int row = idx >> 3;
            int c4 = (idx & 7) << 2;
            cp_async16(as_base + ((buf * 64 + row) * GPW + c4) * 4u,
                       &A[(size_t)(bm + row) * K + k0 + c4]);
        }
#pragma unroll
        for (int p = 0; p < 4; p++) {
            int idx = tid + p * 256;
            int row = idx >> 3;
            int c4 = (idx & 7) << 2;
            cp_async16(bs_base + ((buf * 128 + row) * GPW + c4) * 4u,
                       &Bm[(size_t)(bn + row) * K + k0 + c4]);
        }
        cp_commit();
    };

    prefetch(0, 0);
    int buf = 0;
    const int niter = K / GBK;

    for (int it = 0; it < niter; it++) {
        cp_wait0();
        __syncthreads();
        if (it + 1 < niter) prefetch((it + 1) * GBK, buf ^ 1);

#pragma unroll
        for (int ks = 0; ks < 4; ks++) {
            int kk = ks * 8;
            uint32_t af[2][4], bf[4][2];
#pragma unroll
            for (int mi = 0; mi < 2; mi++) {
                int r = wm + mi * 16 + gid;
                af[mi][0] = f2tf32(As[buf][r    ][kk + tig]);
                af[mi][1] = f2tf32(As[buf][r + 8][kk + tig]);
                af[mi][2] = f2tf32(As[buf][r    ][kk + tig + 4]);
                af[mi][3] = f2tf32(As[buf][r + 8][kk + tig + 4]);
            }
#pragma unroll
            for (int ni = 0; ni < 4; ni++) {
                int r = wn + ni * 8 + gid;
                bf[ni][0] = f2tf32(Bs[buf][r][kk + tig]);
                bf[ni][1] = f2tf32(Bs[buf][r][kk + tig + 4]);
            }
#pragma unroll
            for (int mi = 0; mi < 2; mi++)
#pragma unroll
                for (int ni = 0; ni < 4; ni++)
                    mma_tf32(acc[mi][ni], af[mi], bf[ni]);
        }
        __syncthreads();
        buf ^= 1;
    }

#pragma unroll
    for (int mi = 0; mi < 2; mi++) {
#pragma unroll
        for (int ni = 0; ni < 4; ni++) {
            int row = bm + wm + mi * 16 + gid;
            int col = bn + wn + ni * 8 + tig * 2;
            *(float2*)&Cout[(size_t)row * N + col] =
                make_float2(acc[mi][ni][0], acc[mi][ni][1]);
            *(float2*)&Cout[(size_t)(row + 8) * N + col] =
                make_float2(acc[mi][ni][2], acc[mi][ni][3]);
        }
    }
}

// ---------------- tensor-core split-KV flash attention (TS=64) --------------
// R14 config (persistent Q regs, natural occupancy); redundant end-of-tile
// barrier removed (tile-start barrier provides the ordering).
#define KSP 68
#define VSP 72
__global__ __launch_bounds__(256)
void attn_mma_kernel(const float* __restrict__ cache_k,
                     const float* __restrict__ cache_v,
                     const int* __restrict__ end_offset)
{
    __shared__ __align__(16) float Ks[2][TS][KSP];
    __shared__ __align__(16) float Vs[2][TS][VSP];

    const int bh = blockIdx.x;
    const int chunk = blockIdx.y;
    const int b = bh / PH;
    const int tid = threadIdx.x;
    const int warp = tid >> 5;
    const int lane = tid & 31;
    const int gid = lane >> 2;
    const int tig = lane & 3;
    const int stripe = warp * 16;

    const int end = end_offset[b];
    const int last = end + PT - 1;
    const int end_index = last % PCAP;
    const int new_end = end + PT;    // exec_mask all-true by construction

    const uint32_t ks_base = (uint32_t)__cvta_generic_to_shared(&Ks[0][0][0]);
    const uint32_t vs_base = (uint32_t)__cvta_generic_to_shared(&Vs[0][0][0]);

    float m0 = -1e30f, m1 = -1e30f, l0 = 0.f, l1 = 0.f;
    const int tsq0 = end + stripe + gid;
    const int tsq1 = tsq0 + 8;

    float o[8][4];
#pragma unroll
    for (int ni = 0; ni < 8; ni++)
#pragma unroll
        for (int c = 0; c < 4; c++) o[ni][c] = 0.f;

    const size_t kv_base_new   = (size_t)bh * PT * PD;
    const size_t kv_base_cache = (size_t)bh * PCAP * PD;
    const int s_begin = chunk * CHUNK;

    int n_active = (new_end - s_begin + TS - 1) >> 6;
    if (n_active < 0) n_active = 0;
    if (n_active > NT) n_active = NT;

    const int w0 = end & (PCAP - 1);
    const int w1 = last & (PCAP - 1);
    const bool wrapped = w1 < w0;

    uint32_t qa[8][4];
    if (n_active > 0) {
        const float* qbase = &g_q[(size_t)bh * PT * PD];
        int r0 = stripe + gid, r1 = stripe + gid + 8;
#pragma unroll
        for (int kt = 0; kt < 8; kt++) {
            qa[kt][0] = f2tf32(qbase[r0 * PD + kt * 8 + tig]);
            qa[kt][1] = f2tf32(qbase[r1 * PD + kt * 8 + tig]);
            qa[kt][2] = f2tf32(qbase[r0 * PD + kt * 8 + tig + 4]);
            qa[kt][3] = f2tf32(qbase[r1 * PD + kt * 8 + tig + 4]);
        }
    }

    auto prefetch = [&](int tile, int buf) {
        const int s0 = s_begin + tile * TS;
#pragma unroll
        for (int p = 0; p < 4; p++) {
            int idx = tid + p * 256;     // 0..1023: 64 slots x 16 float4
            int slot = idx >> 4;
            int c4 = (idx & 15) * 4;
            int s = s0 + slot;
            int trel = s - end; if (trel < 0) trel += PCAP;
            const float *srcK, *srcV;
            if (trel < PT) {
                srcK = &g_kn[kv_base_new + (size_t)trel * PD];
                srcV = &g_vn[kv_base_new + (size_t)trel * PD];
            } else {
                srcK = &cache_k[kv_base_cache + (size_t)s * PD];
                srcV = &cache_v[kv_base_cache + (size_t)s * PD];
            }
            cp_async16(ks_base + ((buf * TS + slot) * KSP + c4) * 4u, srcK + c4);
            cp_async16(vs_base + ((buf * TS + slot) * VSP + c4) * 4u, srcV + c4);
        }
        cp_commit();
    };

    if (n_active > 0) prefetch(0, 0);
    int buf = 0;

    for (int tile = 0; tile < n_active; tile++) {
        const int s0 = s_begin + tile * TS;
        const int s_last = s0 + TS - 1;
        const bool has_new = wrapped ? ((s_last >= w0) | (s0 <= w1))
                                     : ((s_last >= w0) & (s0 <= w1));
        const bool has_inv = (s_last >= new_end);
        const bool needs_mask = has_new | has_inv;

        cp_wait0();
        __syncthreads();   // tile data visible AND all warps done with prev tile

        if (tile + 1 < n_active) prefetch(tile + 1, buf ^ 1);

        // ---- S = Q K^T : per warp 16x64 ----
        float sacc[8][4];
        uint32_t* sbits = reinterpret_cast<uint32_t*>(&sacc[0][0]);
#pragma unroll
        for (int ni = 0; ni < 8; ni++)
#pragma unroll
            for (int c = 0; c < 4; c++) sacc[ni][c] = 0.f;
#pragma unroll
        for (int kt = 0; kt < 8; kt++) {
            uint32_t bf[8][2];
#pragma unroll
            for (int ni = 0; ni < 8; ni++) {
                bf[ni][0] = f2tf32(Ks[buf][ni * 8 + gid][kt * 8 + tig]);
                bf[ni][1] = f2tf32(Ks[buf][ni * 8 + gid][kt * 8 + tig + 4]);
            }
#pragma unroll
            for (int ni = 0; ni < 8; ni++)
                mma_tf32(sacc[ni], qa[kt], bf[ni]);
        }

        // ---- mask + scale ----
        if (needs_mask) {
#pragma unroll
            for (int ni = 0; ni < 8; ni++) {
#pragma unroll
                for (int half = 0; half < 2; half++) {
                    int col = ni * 8 + 2 * tig + half;
                    int s = s0 + col;
                    int delta = s - end_index;
                    int p = (delta <= 0) ? (last + delta) : (last + delta - PCAP);
                    if (s >= new_end) p = -1;
                    int d0 = tsq0 - p, d1 = tsq1 - p;
                    bool v0 = (p >= 0) & (d0 >= 0) & (d0 < PCAP);
                    bool v1 = (p >= 0) & (d1 >= 0) & (d1 < PCAP);
                    sacc[ni][half]     = v0 ? sacc[ni][half] * 0.125f     : -1e9f;
                    sacc[ni][half + 2] = v1 ? sacc[ni][half + 2] * 0.125f : -1e9f;
                }
            }
        } else {
#pragma unroll
            for (int ni = 0; ni < 8; ni++)
#pragma unroll
                for (int c = 0; c < 4; c++) sacc[ni][c] *= 0.125f;
        }

        // ---- register softmax ----
        float mx0 = -1e30f, mx1 = -1e30f;
#pragma unroll
        for (int ni = 0; ni < 8; ni++) {
            mx0 = fmaxf(mx0, fmaxf(sacc[ni][0], sacc[ni][1]));
            mx1 = fmaxf(mx1, fmaxf(sacc[ni][2], sacc[ni][3]));
        }
        mx0 = fmaxf(mx0, __shfl_xor_sync(0xFFFFFFFFu, mx0, 1));
        mx0 = fmaxf(mx0, __shfl_xor_sync(0xFFFFFFFFu, mx0, 2));
        mx1 = fmaxf(mx1, __shfl_xor_sync(0xFFFFFFFFu, mx1, 1));
        mx1 = fmaxf(mx1, __shfl_xor_sync(0xFFFFFFFFu, mx1, 2));
        float mn0 = fmaxf(m0, mx0), mn1 = fmaxf(m1, mx1);
        float a0 = __expf(m0 - mn0), a1 = __expf(m1 - mn1);
        m0 = mn0; m1 = mn1;

        float ls0 = 0.f, ls1 = 0.f;
#pragma unroll
        for (int ni = 0; ni < 8; ni++) {
            float p0 = __expf(sacc[ni][0] - mn0);
            float p1 = __expf(sacc[ni][1] - mn0);
            float p2 = __expf(sacc[ni][2] - mn1);
            float p3 = __expf(sacc[ni][3] - mn1);
            ls0 += p0 + p1;  ls1 += p2 + p3;
            sbits[ni * 4 + 0] = f2tf32(p0); sbits[ni * 4 + 1] = f2tf32(p1);
            sbits[ni * 4 + 2] = f2tf32(p2); sbits[ni * 4 + 3] = f2tf32(p3);
        }
        ls0 += __shfl_xor_sync(0xFFFFFFFFu, ls0, 1);
        ls0 += __shfl_xor_sync(0xFFFFFFFFu, ls0, 2);
        ls1 += __shfl_xor_sync(0xFFFFFFFFu, ls1, 1);
        ls1 += __shfl_xor_sync(0xFFFFFFFFu, ls1, 2);
        l0 = l0 * a0 + ls0;
        l1 = l1 * a1 + ls1;

        // ---- rescale O ----
#pragma unroll
        for (int ni = 0; ni < 8; ni++) {
            o[ni][0] *= a0; o[ni][1] *= a0;
            o[ni][2] *= a1; o[ni][3] *= a1;
        }

        // ---- O += P V : shfl permute C-frag -> A-frag (8 k-chunks) ----
        const int lbase = lane & ~3;
        const int lsrc0 = lbase + (tig >> 1);
        const int lsrc2 = lsrc0 + 2;
        const bool odd = tig & 1;
#pragma unroll
        for (int kt = 0; kt < 8; kt++) {
            uint32_t x0 = __shfl_sync(0xFFFFFFFFu, sbits[kt * 4 + 0], lsrc0);
            uint32_t x1 = __shfl_sync(0xFFFFFFFFu, sbits[kt * 4 + 1], lsrc0);
            uint32_t y0 = __shfl_sync(0xFFFFFFFFu, sbits[kt * 4 + 2], lsrc0);
            uint32_t y1 = __shfl_sync(0xFFFFFFFFu, sbits[kt * 4 + 3], lsrc0);
            uint32_t x2 = __shfl_sync(0xFFFFFFFFu, sbits[kt * 4 + 0], lsrc2);
            uint32_t x3 = __shfl_sync(0xFFFFFFFFu, sbits[kt * 4 + 1], lsrc2);
            uint32_t y2 = __shfl_sync(0xFFFFFFFFu, sbits[kt * 4 + 2], lsrc2);
            uint32_t y3 = __shfl_sync(0xFFFFFFFFu, sbits[kt * 4 + 3], lsrc2);
            uint32_t pa[4];
            pa[0] = odd ? x1 : x0;
            pa[1] = odd ? y1 : y0;
            pa[2] = odd ? x3 : x2;
            pa[3] = odd ? y3 : y2;
#pragma unroll
            for (int ni = 0; ni < 8; ni++) {
                uint32_t bf[2];
                bf[0] = f2tf32(Vs[buf][kt * 8 + tig    ][ni * 8 + gid]);
                bf[1] = f2tf32(Vs[buf][kt * 8 + tig + 4][ni * 8 + gid]);
                mma_tf32(o[ni], pa, bf);
            }
        }
        buf ^= 1;   // end-of-tile barrier removed: next tile-start barrier orders reuse
    }

    const size_t prowbase = (size_t)(chunk * PB * PH + bh) * PT;
    {
        int r0 = stripe + gid, r1 = stripe + gid + 8;
#pragma unroll
        for (int ni = 0; ni < 8; ni++) {
            int col = ni * 8 + tig * 2;
            *(float2*)&g_po[(prowbase + r0) * PD + col] = make_float2(o[ni][0], o[ni][1]);
            *(float2*)&g_po[(prowbase + r1) * PD + col] = make_float2(o[ni][2], o[ni][3]);
        }
        if (tig == 0) {
            g_pm[prowbase + r0] = m0;  g_pl[prowbase + r0] = l0;
            g_pm[prowbase + r1] = m1;  g_pl[prowbase + r1] = l1;
        }
    }
}

// ---------------- combine partials -----------------------------------------
__global__ __launch_bounds__(256)
void attn_combine_kernel()
{
    int gid = blockIdx.x * 256 + threadIdx.x;
    int row = gid >> 4;
    int q4 = (gid & 15) << 2;

    const int RSTRIDE = PB * PH * PT;
    float mv[NCHUNK];
    float mx = -1e30f;
#pragma unroll
    for (int c = 0; c < NCHUNK; c++) {
        mv[c] = g_pm[c * RSTRIDE + row];
        mx = fmaxf(mx, mv[c]);
    }
    float l = 0.f;
    float4 acc = make_float4(0.f, 0.f, 0.f, 0.f);
#pragma unroll
    for (int c = 0; c < NCHUNK; c++) {
        float w = __expf(mv[c] - mx);
        l = fmaf(g_pl[c * RSTRIDE + row], w, l);
        float4 v = *(const float4*)&g_po[((size_t)(c * RSTRIDE) + row) * PD + q4];
        acc.x = fmaf(w, v.x, acc.x); acc.y = fmaf(w, v.y, acc.y);
        acc.z = fmaf(w, v.z, acc.z); acc.w = fmaf(w, v.w, acc.w);
    }
    float inv = 1.0f / l;

    int b = row >> 11;
    int h = (row >> 7) & (PH - 1);
    int t = row & (PT - 1);
    float* op = &g_att[(size_t)(b * PT + t) * PC + h * PD + q4];
    *(float4*)op = make_float4(acc.x * inv, acc.y * inv, acc.z * inv, acc.w * inv);
}

// ---------------- launch ---------------------------------------------------
extern "C" void kernel_launch(void* const* d_in, const int* in_sizes, int n_in,
                              void* d_out, int out_size)
{
    const float* x       = (const float*)d_in[0];
    const float* w_in    = (const float*)d_in[1];
    const float* w_out   = (const float*)d_in[2];
    const float* cache_k = (const float*)d_in[3];
    const float* cache_v = (const float*)d_in[4];
    const int*   end_off = (const int*)d_in[5];
    float* out = (float*)d_out;

    float* att;  cudaGetSymbolAddress((void**)&att,  g_att);

    rope_trig_kernel<<<(M1 * PHALF) / 256, 256>>>(end_off);
    gemm_qkv_tf32_kernel<<<dim3(N1 / 128, M1 / 64), 256>>>(x, w_in);
    attn_mma_kernel<<<dim3(PB * PH, NCHUNK), 256>>>(cache_k, cache_v, end_off);
    attn_combine_kernel<<<(PB * PH * PT * PD / 4) / 256, 256>>>();
    gemm_nt_tf32_kernel<<<dim3(PC / 128, M1 / 64), 256>>>(att, w_out, out, M1, PC, PC);
}